// round 6
// baseline (speedup 1.0000x reference)
#include <cuda_runtime.h>
#include <cstdint>

#define B_    8
#define N1_   16384
#define N2_   2048
#define C1_   128
#define C2_   256
#define INCH_ 384
#define H1_   256
#define H2_   128
#define M_    (B_ * N1_)            // 131072 rows
#define STAT_ROWS 256
#define STAT_BLKS (M_ / STAT_ROWS)  // 512
#define BN_EPS 1e-5f

// ---------------- scratch (device globals; no cudaMalloc allowed) ----------------
__device__ float g_x  [(size_t)M_ * INCH_];   // concat(points1, interp)  [M,384]
__device__ float g_h1 [(size_t)M_ * H1_];     // GEMM1 out (pre-BN)       [M,256]
__device__ float g_h2 [(size_t)M_ * H2_];     // GEMM2 out (pre-BN)       [M,128]
__device__ float g_Wt1[INCH_ * H1_];          // W1^T  [K=384][N=256]
__device__ float g_Wt2[H1_ * H2_];            // W2^T  [K=256][N=128]
__device__ float g_psum[STAT_BLKS * H1_];
__device__ float g_psq [STAT_BLKS * H1_];
__device__ float g_scale1[H1_], g_shift1[H1_];
__device__ float g_scale2[H2_], g_shift2[H2_];

// ---------------- weight transpose: Wt[k][o] = W[o][k] ----------------
__global__ void transpose_kernel(const float* __restrict__ W, float* __restrict__ Wt,
                                 int O, int I) {
    int idx = blockIdx.x * 256 + threadIdx.x;
    if (idx < O * I) {
        int o = idx / I, i = idx % I;
        Wt[i * O + o] = W[idx];
    }
}

// ---------------- 3-NN + interpolation + concat ----------------
// 4 queries per thread: candidate coords loaded from smem ONCE per j and
// reused across 4 queries; insertion guarded by a single rarely-taken compare.
#define QPT 4
#define KNN_T 128
#define QPB (QPT * KNN_T)   // 512 queries per block

__global__ __launch_bounds__(KNN_T)
void knn_interp_kernel(const float* __restrict__ xyz1, const float* __restrict__ xyz2,
                       const float* __restrict__ points1, const float* __restrict__ points2,
                       float* __restrict__ x_out) {
    __shared__ float sx[N2_], sy[N2_], sz[N2_];
    __shared__ int   s_idx[QPB][3];
    __shared__ float s_w  [QPB][3];

    const int b   = blockIdx.y;
    const int q0  = blockIdx.x * QPB;
    const int tid = threadIdx.x;

    const float* x2 = xyz2 + (size_t)b * N2_ * 3;
    for (int j = tid; j < N2_; j += KNN_T) {
        float3 v = ((const float3*)x2)[j];
        sx[j] = v.x; sy[j] = v.y; sz[j] = v.z;
    }
    __syncthreads();

    // ---- phase 1: top-3 smallest distances for 4 queries per thread ----
    float px[QPT], py[QPT], pz[QPT];
    float d0[QPT], d1[QPT], d2[QPT];
    int   i0[QPT], i1[QPT], i2[QPT];
#pragma unroll
    for (int i = 0; i < QPT; i++) {
        const int q = q0 + i * KNN_T + tid;
        float3 p = ((const float3*)(xyz1 + (size_t)b * N1_ * 3))[q];
        px[i] = p.x; py[i] = p.y; pz[i] = p.z;
        d0[i] = 1e30f; d1[i] = 1e30f; d2[i] = 1e30f;
        i0[i] = 0; i1[i] = 0; i2[i] = 0;
    }

#pragma unroll 4
    for (int j = 0; j < N2_; j++) {
        const float cx = sx[j], cy = sy[j], cz = sz[j];
#pragma unroll
        for (int i = 0; i < QPT; i++) {
            float dx = px[i] - cx;
            float dy = py[i] - cy;
            float dz = pz[i] - cz;
            float d  = fmaf(dx, dx, fmaf(dy, dy, dz * dz));
            if (d < d2[i]) {                       // rare
                if (d < d0[i])      { d2[i]=d1[i]; i2[i]=i1[i]; d1[i]=d0[i]; i1[i]=i0[i]; d0[i]=d; i0[i]=j; }
                else if (d < d1[i]) { d2[i]=d1[i]; i2[i]=i1[i]; d1[i]=d;  i1[i]=j; }
                else                { d2[i]=d;  i2[i]=j; }
            }
        }
    }

#pragma unroll
    for (int i = 0; i < QPT; i++) {
        float a0 = 1.0f / fmaxf(d0[i], 1e-10f);
        float a1 = 1.0f / fmaxf(d1[i], 1e-10f);
        float a2 = 1.0f / fmaxf(d2[i], 1e-10f);
        float inv = 1.0f / fmaxf(a0 + a1 + a2, 1e-8f);
        const int lq = i * KNN_T + tid;
        s_idx[lq][0] = i0[i]; s_idx[lq][1] = i1[i]; s_idx[lq][2] = i2[i];
        s_w[lq][0] = a0 * inv; s_w[lq][1] = a1 * inv; s_w[lq][2] = a2 * inv;
    }
    __syncthreads();

    // ---- phase 2: warp-cooperative gather + concat write ----
    const int warp = tid >> 5, lane = tid & 31;
    const float* p2  = points2 + (size_t)b * N2_ * C2_;
    const float* p1b = points1 + ((size_t)b * N1_ + q0) * C1_;
    float* xb = x_out + ((size_t)b * N1_ + q0) * INCH_;

    for (int lq = warp; lq < QPB; lq += 4) {
        const int   j0 = s_idx[lq][0], j1 = s_idx[lq][1], j2 = s_idx[lq][2];
        const float a0 = s_w[lq][0],   a1 = s_w[lq][1],   a2 = s_w[lq][2];
        const float* r0 = p2 + (size_t)j0 * C2_;
        const float* r1 = p2 + (size_t)j1 * C2_;
        const float* r2 = p2 + (size_t)j2 * C2_;
        float* xrow = xb + (size_t)lq * INCH_;
#pragma unroll
        for (int c = lane; c < C2_; c += 32)
            xrow[C1_ + c] = fmaf(a0, r0[c], fmaf(a1, r1[c], a2 * r2[c]));
        const float* pr = p1b + (size_t)lq * C1_;
#pragma unroll
        for (int c = lane; c < C1_; c += 32)
            xrow[c] = pr[c];
    }
}

// ---------------- SGEMM: C[M,N] = op(A)[M,K] @ Bt[K,N] ----------------
// 128x128 tile, BK=16, 256 threads, 8x8 microtile, double-buffered smem,
// register prefetch of the next tile, ONE __syncthreads per k-tile.
// Optional fused BN+ReLU on A (per-K-channel scale/shift then max(.,0)).
template <int K, int N, bool BN>
__global__ __launch_bounds__(256)
void gemm_kernel(const float* __restrict__ A, const float* __restrict__ Bt,
                 const float* __restrict__ scale, const float* __restrict__ shift,
                 float* __restrict__ C) {
    __shared__ float As[2][16][128];
    __shared__ float Bs[2][16][128];

    const int tid = threadIdx.x;
    const int m0 = blockIdx.x * 128;
    const int n0 = blockIdx.y * 128;

    // A staging: warp = 32 consecutive rows, same 8-col group (conflict-free STS)
    const int ar  = tid & 127;
    const int ac  = (tid >> 7) * 8;           // 0 or 8
    // B staging
    const int br  = tid >> 4;                 // 0..15
    const int bc  = (tid & 15) * 8;
    // microtile
    const int ty = tid >> 4, tx = tid & 15;

    const float* Ap = A + (size_t)(m0 + ar) * K + ac;
    const float* Bp = Bt + (size_t)br * N + n0 + bc;

    float4 pa0, pa1, pb0, pb1;

    // prologue: tile 0 -> smem[0]
    {
        pa0 = *(const float4*)(Ap + 0);
        pa1 = *(const float4*)(Ap + 4);
        pb0 = *(const float4*)(Bp + 0);
        pb1 = *(const float4*)(Bp + 4);
        if (BN) {
            const float* sc = scale + ac; const float* sh = shift + ac;
            pa0.x = fmaxf(fmaf(pa0.x, sc[0], sh[0]), 0.f);
            pa0.y = fmaxf(fmaf(pa0.y, sc[1], sh[1]), 0.f);
            pa0.z = fmaxf(fmaf(pa0.z, sc[2], sh[2]), 0.f);
            pa0.w = fmaxf(fmaf(pa0.w, sc[3], sh[3]), 0.f);
            pa1.x = fmaxf(fmaf(pa1.x, sc[4], sh[4]), 0.f);
            pa1.y = fmaxf(fmaf(pa1.y, sc[5], sh[5]), 0.f);
            pa1.z = fmaxf(fmaf(pa1.z, sc[6], sh[6]), 0.f);
            pa1.w = fmaxf(fmaf(pa1.w, sc[7], sh[7]), 0.f);
        }
        As[0][ac+0][ar]=pa0.x; As[0][ac+1][ar]=pa0.y; As[0][ac+2][ar]=pa0.z; As[0][ac+3][ar]=pa0.w;
        As[0][ac+4][ar]=pa1.x; As[0][ac+5][ar]=pa1.y; As[0][ac+6][ar]=pa1.z; As[0][ac+7][ar]=pa1.w;
        *(float4*)&Bs[0][br][bc]   = pb0;
        *(float4*)&Bs[0][br][bc+4] = pb1;
    }
    __syncthreads();

    float acc[8][8];
#pragma unroll
    for (int i = 0; i < 8; i++)
#pragma unroll
        for (int j = 0; j < 8; j++) acc[i][j] = 0.0f;

    const int KT = K / 16;
#pragma unroll 1
    for (int kt = 0; kt < KT; kt++) {
        const int cur = kt & 1;
        const bool more = (kt + 1 < KT);
        if (more) {
            const int k0 = (kt + 1) * 16;
            pa0 = *(const float4*)(Ap + k0 + 0);
            pa1 = *(const float4*)(Ap + k0 + 4);
            pb0 = *(const float4*)(Bp + (size_t)k0 * N + 0);
            pb1 = *(const float4*)(Bp + (size_t)k0 * N + 4);
            if (BN) {
                const float* sc = scale + k0 + ac; const float* sh = shift + k0 + ac;
                pa0.x = fmaxf(fmaf(pa0.x, sc[0], sh[0]), 0.f);
                pa0.y = fmaxf(fmaf(pa0.y, sc[1], sh[1]), 0.f);
                pa0.z = fmaxf(fmaf(pa0.z, sc[2], sh[2]), 0.f);
                pa0.w = fmaxf(fmaf(pa0.w, sc[3], sh[3]), 0.f);
                pa1.x = fmaxf(fmaf(pa1.x, sc[4], sh[4]), 0.f);
                pa1.y = fmaxf(fmaf(pa1.y, sc[5], sh[5]), 0.f);
                pa1.z = fmaxf(fmaf(pa1.z, sc[6], sh[6]), 0.f);
                pa1.w = fmaxf(fmaf(pa1.w, sc[7], sh[7]), 0.f);
            }
        }

#pragma unroll
        for (int k = 0; k < 16; k++) {
            float a[8], bb[8];
            *(float4*)(a)      = *(const float4*)&As[cur][k][ty * 8];
            *(float4*)(a + 4)  = *(const float4*)&As[cur][k][ty * 8 + 4];
            *(float4*)(bb)     = *(const float4*)&Bs[cur][k][tx * 8];
            *(float4*)(bb + 4) = *(const float4*)&Bs[cur][k][tx * 8 + 4];
#pragma unroll
            for (int i = 0; i < 8; i++)
#pragma unroll
                for (int j = 0; j < 8; j++)
                    acc[i][j] = fmaf(a[i], bb[j], acc[i][j]);
        }

        if (more) {
            const int nxt = cur ^ 1;
            As[nxt][ac+0][ar]=pa0.x; As[nxt][ac+1][ar]=pa0.y; As[nxt][ac+2][ar]=pa0.z; As[nxt][ac+3][ar]=pa0.w;
            As[nxt][ac+4][ar]=pa1.x; As[nxt][ac+5][ar]=pa1.y; As[nxt][ac+6][ar]=pa1.z; As[nxt][ac+7][ar]=pa1.w;
            *(float4*)&Bs[nxt][br][bc]   = pb0;
            *(float4*)&Bs[nxt][br][bc+4] = pb1;
            __syncthreads();
        }
    }

#pragma unroll
    for (int i = 0; i < 8; i++) {
        float* cp = C + (size_t)(m0 + ty * 8 + i) * N + n0 + tx * 8;
        *(float4*)(cp)     = make_float4(acc[i][0], acc[i][1], acc[i][2], acc[i][3]);
        *(float4*)(cp + 4) = make_float4(acc[i][4], acc[i][5], acc[i][6], acc[i][7]);
    }
}

// ---------------- BN stats: per-block partial sums (deterministic) ----------------
template <int C>
__global__ void stats_kernel(const float* __restrict__ H,
                             float* __restrict__ psum, float* __restrict__ psq) {
    const int c = threadIdx.x;  // C threads
    size_t base = (size_t)blockIdx.x * STAT_ROWS * C + c;
    float s = 0.0f, s2 = 0.0f;
#pragma unroll 4
    for (int r = 0; r < STAT_ROWS; r++) {
        float v = H[base + (size_t)r * C];
        s += v;
        s2 = fmaf(v, v, s2);
    }
    psum[blockIdx.x * C + c] = s;
    psq [blockIdx.x * C + c] = s2;
}

template <int C>
__global__ void reduce_kernel(const float* __restrict__ psum, const float* __restrict__ psq,
                              const float* __restrict__ gamma, const float* __restrict__ beta,
                              float* __restrict__ scale, float* __restrict__ shift) {
    const int c = threadIdx.x;
    float s = 0.0f, s2 = 0.0f;
    for (int i = 0; i < STAT_BLKS; i++) {
        s  += psum[i * C + c];
        s2 += psq [i * C + c];
    }
    const float invn = 1.0f / (float)M_;
    float mean = s * invn;
    float var  = s2 * invn - mean * mean;
    float sc = gamma[c] * rsqrtf(var + BN_EPS);
    scale[c] = sc;
    shift[c] = beta[c] - mean * sc;
}

// ---------------- final BN2 + ReLU ----------------
__global__ void apply_kernel(const float* __restrict__ H,
                             const float* __restrict__ scale, const float* __restrict__ shift,
                             float* __restrict__ out) {
    size_t i = (size_t)blockIdx.x * blockDim.x + threadIdx.x;   // float4 index
    float4 v = ((const float4*)H)[i];
    int c = (int)((i * 4) & (H2_ - 1));
    float4 o;
    o.x = fmaxf(fmaf(v.x, scale[c + 0], shift[c + 0]), 0.0f);
    o.y = fmaxf(fmaf(v.y, scale[c + 1], shift[c + 1]), 0.0f);
    o.z = fmaxf(fmaf(v.z, scale[c + 2], shift[c + 2]), 0.0f);
    o.w = fmaxf(fmaf(v.w, scale[c + 3], shift[c + 3]), 0.0f);
    ((float4*)out)[i] = o;
}

// ---------------- host launcher ----------------
extern "C" void kernel_launch(void* const* d_in, const int* in_sizes, int n_in,
                              void* d_out, int out_size) {
    const float* xyz1    = (const float*)d_in[0];
    const float* xyz2    = (const float*)d_in[1];
    const float* points1 = (const float*)d_in[2];
    const float* points2 = (const float*)d_in[3];
    const float* W1      = (const float*)d_in[4];
    // d_in[5] = b1 : cancels under BatchNorm (mean subtraction) -> unused
    const float* gamma1  = (const float*)d_in[6];
    const float* beta1   = (const float*)d_in[7];
    const float* W2      = (const float*)d_in[8];
    // d_in[9] = b2 : cancels under BatchNorm -> unused
    const float* gamma2  = (const float*)d_in[10];
    const float* beta2   = (const float*)d_in[11];
    float* out = (float*)d_out;

    float *px, *ph1, *ph2, *pwt1, *pwt2, *pps, *ppq, *psc1, *psh1, *psc2, *psh2;
    cudaGetSymbolAddress((void**)&px,   g_x);
    cudaGetSymbolAddress((void**)&ph1,  g_h1);
    cudaGetSymbolAddress((void**)&ph2,  g_h2);
    cudaGetSymbolAddress((void**)&pwt1, g_Wt1);
    cudaGetSymbolAddress((void**)&pwt2, g_Wt2);
    cudaGetSymbolAddress((void**)&pps,  g_psum);
    cudaGetSymbolAddress((void**)&ppq,  g_psq);
    cudaGetSymbolAddress((void**)&psc1, g_scale1);
    cudaGetSymbolAddress((void**)&psh1, g_shift1);
    cudaGetSymbolAddress((void**)&psc2, g_scale2);
    cudaGetSymbolAddress((void**)&psh2, g_shift2);

    // weight transposes (tiny)
    transpose_kernel<<<(H1_ * INCH_ + 255) / 256, 256>>>(W1, pwt1, H1_, INCH_);
    transpose_kernel<<<(H2_ * H1_  + 255) / 256, 256>>>(W2, pwt2, H2_, H1_);

    // 3-NN + interpolate + concat -> g_x [M,384]
    {
        dim3 grid(N1_ / QPB, B_);
        knn_interp_kernel<<<grid, KNN_T>>>(xyz1, xyz2, points1, points2, px);
    }

    // GEMM1: g_h1 = g_x @ W1^T   (bias dropped: cancels in BN)
    {
        dim3 grid(M_ / 128, H1_ / 128);
        gemm_kernel<INCH_, H1_, false><<<grid, 256>>>(px, pwt1, nullptr, nullptr, ph1);
    }

    // BN1 stats -> scale1/shift1
    stats_kernel<H1_><<<STAT_BLKS, H1_>>>(ph1, pps, ppq);
    reduce_kernel<H1_><<<1, H1_>>>(pps, ppq, gamma1, beta1, psc1, psh1);

    // GEMM2 with fused BN1+ReLU on the A operand: g_h2 = relu(bn1(g_h1)) @ W2^T
    {
        dim3 grid(M_ / 128, H2_ / 128);
        gemm_kernel<H1_, H2_, true><<<grid, 256>>>(ph1, pwt2, psc1, psh1, ph2);
    }

    // BN2 stats -> scale2/shift2
    stats_kernel<H2_><<<STAT_BLKS, H2_>>>(ph2, pps, ppq);
    reduce_kernel<H2_><<<1, H2_>>>(pps, ppq, gamma2, beta2, psc2, psh2);

    // final BN2 + ReLU -> d_out [M,128]
    {
        size_t n4 = (size_t)M_ * H2_ / 4;
        apply_kernel<<<(unsigned)(n4 / 256), 256>>>(ph2, psc2, psh2, out);
    }
}

// round 7
// speedup vs baseline: 1.5345x; 1.5345x over previous
#include <cuda_runtime.h>
#include <cstdint>

#define B_    8
#define N1_   16384
#define N2_   2048
#define C1_   128
#define C2_   256
#define INCH_ 384
#define H1_   256
#define H2_   128
#define M_    (B_ * N1_)            // 131072 rows
#define STAT_ROWS 256
#define STAT_BLKS (M_ / STAT_ROWS)  // 512
#define BN_EPS 1e-5f

// ---------------- scratch (device globals; no cudaMalloc allowed) ----------------
__device__ float g_x  [(size_t)M_ * INCH_];   // concat(points1, interp)  [M,384]
__device__ float g_h1 [(size_t)M_ * H1_];     // GEMM1 out (pre-BN)       [M,256]
__device__ float g_h2 [(size_t)M_ * H2_];     // GEMM2 out (pre-BN)       [M,128]
__device__ float g_Wt1[INCH_ * H1_];          // W1^T  [K=384][N=256]
__device__ float g_Wt2[H1_ * H2_];            // W2^T  [K=256][N=128]
__device__ float g_psum[STAT_BLKS * H1_];
__device__ float g_psq [STAT_BLKS * H1_];
__device__ float g_scale1[H1_], g_shift1[H1_];
__device__ float g_scale2[H2_], g_shift2[H2_];

// ---------------- weight transpose: Wt[k][o] = W[o][k] ----------------
__global__ void transpose_kernel(const float* __restrict__ W, float* __restrict__ Wt,
                                 int O, int I) {
    int idx = blockIdx.x * 256 + threadIdx.x;
    if (idx < O * I) {
        int o = idx / I, i = idx % I;
        Wt[i * O + o] = W[idx];
    }
}

// ---------------- 3-NN + interpolation + concat ----------------
// 4 queries per thread: candidate coords loaded from smem ONCE per j and
// reused across 4 queries; insertion guarded by a single rarely-taken compare.
#define QPT 4
#define KNN_T 128
#define QPB (QPT * KNN_T)   // 512 queries per block

__global__ __launch_bounds__(KNN_T)
void knn_interp_kernel(const float* __restrict__ xyz1, const float* __restrict__ xyz2,
                       const float* __restrict__ points1, const float* __restrict__ points2,
                       float* __restrict__ x_out) {
    __shared__ float sx[N2_], sy[N2_], sz[N2_];
    __shared__ int   s_idx[QPB][3];
    __shared__ float s_w  [QPB][3];

    const int b   = blockIdx.y;
    const int q0  = blockIdx.x * QPB;
    const int tid = threadIdx.x;

    const float* x2 = xyz2 + (size_t)b * N2_ * 3;
    for (int j = tid; j < N2_; j += KNN_T) {
        float3 v = ((const float3*)x2)[j];
        sx[j] = v.x; sy[j] = v.y; sz[j] = v.z;
    }
    __syncthreads();

    // ---- phase 1: top-3 smallest distances for 4 queries per thread ----
    float px[QPT], py[QPT], pz[QPT];
    float d0[QPT], d1[QPT], d2[QPT];
    int   i0[QPT], i1[QPT], i2[QPT];
#pragma unroll
    for (int i = 0; i < QPT; i++) {
        const int q = q0 + i * KNN_T + tid;
        float3 p = ((const float3*)(xyz1 + (size_t)b * N1_ * 3))[q];
        px[i] = p.x; py[i] = p.y; pz[i] = p.z;
        d0[i] = 1e30f; d1[i] = 1e30f; d2[i] = 1e30f;
        i0[i] = 0; i1[i] = 0; i2[i] = 0;
    }

#pragma unroll 4
    for (int j = 0; j < N2_; j++) {
        const float cx = sx[j], cy = sy[j], cz = sz[j];
#pragma unroll
        for (int i = 0; i < QPT; i++) {
            float dx = px[i] - cx;
            float dy = py[i] - cy;
            float dz = pz[i] - cz;
            float d  = fmaf(dx, dx, fmaf(dy, dy, dz * dz));
            if (d < d2[i]) {                       // rare
                if (d < d0[i])      { d2[i]=d1[i]; i2[i]=i1[i]; d1[i]=d0[i]; i1[i]=i0[i]; d0[i]=d; i0[i]=j; }
                else if (d < d1[i]) { d2[i]=d1[i]; i2[i]=i1[i]; d1[i]=d;  i1[i]=j; }
                else                { d2[i]=d;  i2[i]=j; }
            }
        }
    }

#pragma unroll
    for (int i = 0; i < QPT; i++) {
        float a0 = 1.0f / fmaxf(d0[i], 1e-10f);
        float a1 = 1.0f / fmaxf(d1[i], 1e-10f);
        float a2 = 1.0f / fmaxf(d2[i], 1e-10f);
        float inv = 1.0f / fmaxf(a0 + a1 + a2, 1e-8f);
        const int lq = i * KNN_T + tid;
        s_idx[lq][0] = i0[i]; s_idx[lq][1] = i1[i]; s_idx[lq][2] = i2[i];
        s_w[lq][0] = a0 * inv; s_w[lq][1] = a1 * inv; s_w[lq][2] = a2 * inv;
    }
    __syncthreads();

    // ---- phase 2: warp-cooperative gather + concat write ----
    const int warp = tid >> 5, lane = tid & 31;
    const float* p2  = points2 + (size_t)b * N2_ * C2_;
    const float* p1b = points1 + ((size_t)b * N1_ + q0) * C1_;
    float* xb = x_out + ((size_t)b * N1_ + q0) * INCH_;

    for (int lq = warp; lq < QPB; lq += 4) {
        const int   j0 = s_idx[lq][0], j1 = s_idx[lq][1], j2 = s_idx[lq][2];
        const float a0 = s_w[lq][0],   a1 = s_w[lq][1],   a2 = s_w[lq][2];
        const float* r0 = p2 + (size_t)j0 * C2_;
        const float* r1 = p2 + (size_t)j1 * C2_;
        const float* r2 = p2 + (size_t)j2 * C2_;
        float* xrow = xb + (size_t)lq * INCH_;
#pragma unroll
        for (int c = lane; c < C2_; c += 32)
            xrow[C1_ + c] = fmaf(a0, r0[c], fmaf(a1, r1[c], a2 * r2[c]));
        const float* pr = p1b + (size_t)lq * C1_;
#pragma unroll
        for (int c = lane; c < C1_; c += 32)
            xrow[c] = pr[c];
    }
}

// ---------------- SGEMM: C[M,N] = op(A)[M,K] @ Bt[K,N] ----------------
// 128x128 tile, BK=16, 256 threads, 8x8 microtile, double-buffered smem,
// register prefetch of the next tile, ONE __syncthreads per k-tile.
// __launch_bounds__(256, 2): cap regs at 128 so 2 CTAs/SM fit (R5 regression:
// 129 regs -> 1 CTA/SM -> occupancy 12.5% -> 2x slowdown).
// Optional fused BN+ReLU on A (per-K-channel scale/shift then max(.,0)).
template <int K, int N, bool BN>
__global__ __launch_bounds__(256, 2)
void gemm_kernel(const float* __restrict__ A, const float* __restrict__ Bt,
                 const float* __restrict__ scale, const float* __restrict__ shift,
                 float* __restrict__ C) {
    __shared__ float As[2][16][128];
    __shared__ float Bs[2][16][128];

    const int tid = threadIdx.x;
    const int m0 = blockIdx.x * 128;
    const int n0 = blockIdx.y * 128;

    // A staging: warp = 32 consecutive rows, same 8-col group (conflict-free STS)
    const int ar  = tid & 127;
    const int ac  = (tid >> 7) * 8;           // 0 or 8
    // B staging
    const int br  = tid >> 4;                 // 0..15
    const int bc  = (tid & 15) * 8;
    // microtile
    const int ty = tid >> 4, tx = tid & 15;

    const float* Ap = A + (size_t)(m0 + ar) * K + ac;
    const float* Bp = Bt + (size_t)br * N + n0 + bc;

    float4 pa0, pa1, pb0, pb1;

    // prologue: tile 0 -> smem[0]
    {
        pa0 = *(const float4*)(Ap + 0);
        pa1 = *(const float4*)(Ap + 4);
        pb0 = *(const float4*)(Bp + 0);
        pb1 = *(const float4*)(Bp + 4);
        if (BN) {
            const float* sc = scale + ac; const float* sh = shift + ac;
            pa0.x = fmaxf(fmaf(pa0.x, sc[0], sh[0]), 0.f);
            pa0.y = fmaxf(fmaf(pa0.y, sc[1], sh[1]), 0.f);
            pa0.z = fmaxf(fmaf(pa0.z, sc[2], sh[2]), 0.f);
            pa0.w = fmaxf(fmaf(pa0.w, sc[3], sh[3]), 0.f);
            pa1.x = fmaxf(fmaf(pa1.x, sc[4], sh[4]), 0.f);
            pa1.y = fmaxf(fmaf(pa1.y, sc[5], sh[5]), 0.f);
            pa1.z = fmaxf(fmaf(pa1.z, sc[6], sh[6]), 0.f);
            pa1.w = fmaxf(fmaf(pa1.w, sc[7], sh[7]), 0.f);
        }
        As[0][ac+0][ar]=pa0.x; As[0][ac+1][ar]=pa0.y; As[0][ac+2][ar]=pa0.z; As[0][ac+3][ar]=pa0.w;
        As[0][ac+4][ar]=pa1.x; As[0][ac+5][ar]=pa1.y; As[0][ac+6][ar]=pa1.z; As[0][ac+7][ar]=pa1.w;
        *(float4*)&Bs[0][br][bc]   = pb0;
        *(float4*)&Bs[0][br][bc+4] = pb1;
    }
    __syncthreads();

    float acc[8][8];
#pragma unroll
    for (int i = 0; i < 8; i++)
#pragma unroll
        for (int j = 0; j < 8; j++) acc[i][j] = 0.0f;

    const int KT = K / 16;
#pragma unroll 1
    for (int kt = 0; kt < KT; kt++) {
        const int cur = kt & 1;
        const bool more = (kt + 1 < KT);
        if (more) {
            const int k0 = (kt + 1) * 16;
            pa0 = *(const float4*)(Ap + k0 + 0);
            pa1 = *(const float4*)(Ap + k0 + 4);
            pb0 = *(const float4*)(Bp + (size_t)k0 * N + 0);
            pb1 = *(const float4*)(Bp + (size_t)k0 * N + 4);
            if (BN) {
                const float* sc = scale + k0 + ac; const float* sh = shift + k0 + ac;
                pa0.x = fmaxf(fmaf(pa0.x, sc[0], sh[0]), 0.f);
                pa0.y = fmaxf(fmaf(pa0.y, sc[1], sh[1]), 0.f);
                pa0.z = fmaxf(fmaf(pa0.z, sc[2], sh[2]), 0.f);
                pa0.w = fmaxf(fmaf(pa0.w, sc[3], sh[3]), 0.f);
                pa1.x = fmaxf(fmaf(pa1.x, sc[4], sh[4]), 0.f);
                pa1.y = fmaxf(fmaf(pa1.y, sc[5], sh[5]), 0.f);
                pa1.z = fmaxf(fmaf(pa1.z, sc[6], sh[6]), 0.f);
                pa1.w = fmaxf(fmaf(pa1.w, sc[7], sh[7]), 0.f);
            }
        }

#pragma unroll
        for (int k = 0; k < 16; k++) {
            float a[8], bb[8];
            *(float4*)(a)      = *(const float4*)&As[cur][k][ty * 8];
            *(float4*)(a + 4)  = *(const float4*)&As[cur][k][ty * 8 + 4];
            *(float4*)(bb)     = *(const float4*)&Bs[cur][k][tx * 8];
            *(float4*)(bb + 4) = *(const float4*)&Bs[cur][k][tx * 8 + 4];
#pragma unroll
            for (int i = 0; i < 8; i++)
#pragma unroll
                for (int j = 0; j < 8; j++)
                    acc[i][j] = fmaf(a[i], bb[j], acc[i][j]);
        }

        if (more) {
            const int nxt = cur ^ 1;
            As[nxt][ac+0][ar]=pa0.x; As[nxt][ac+1][ar]=pa0.y; As[nxt][ac+2][ar]=pa0.z; As[nxt][ac+3][ar]=pa0.w;
            As[nxt][ac+4][ar]=pa1.x; As[nxt][ac+5][ar]=pa1.y; As[nxt][ac+6][ar]=pa1.z; As[nxt][ac+7][ar]=pa1.w;
            *(float4*)&Bs[nxt][br][bc]   = pb0;
            *(float4*)&Bs[nxt][br][bc+4] = pb1;
            __syncthreads();
        }
    }

#pragma unroll
    for (int i = 0; i < 8; i++) {
        float* cp = C + (size_t)(m0 + ty * 8 + i) * N + n0 + tx * 8;
        *(float4*)(cp)     = make_float4(acc[i][0], acc[i][1], acc[i][2], acc[i][3]);
        *(float4*)(cp + 4) = make_float4(acc[i][4], acc[i][5], acc[i][6], acc[i][7]);
    }
}

// ---------------- BN stats: per-block partial sums (deterministic) ----------------
template <int C>
__global__ void stats_kernel(const float* __restrict__ H,
                             float* __restrict__ psum, float* __restrict__ psq) {
    const int c = threadIdx.x;  // C threads
    size_t base = (size_t)blockIdx.x * STAT_ROWS * C + c;
    float s = 0.0f, s2 = 0.0f;
#pragma unroll 4
    for (int r = 0; r < STAT_ROWS; r++) {
        float v = H[base + (size_t)r * C];
        s += v;
        s2 = fmaf(v, v, s2);
    }
    psum[blockIdx.x * C + c] = s;
    psq [blockIdx.x * C + c] = s2;
}

template <int C>
__global__ void reduce_kernel(const float* __restrict__ psum, const float* __restrict__ psq,
                              const float* __restrict__ gamma, const float* __restrict__ beta,
                              float* __restrict__ scale, float* __restrict__ shift) {
    const int c = threadIdx.x;
    float s = 0.0f, s2 = 0.0f;
    for (int i = 0; i < STAT_BLKS; i++) {
        s  += psum[i * C + c];
        s2 += psq [i * C + c];
    }
    const float invn = 1.0f / (float)M_;
    float mean = s * invn;
    float var  = s2 * invn - mean * mean;
    float sc = gamma[c] * rsqrtf(var + BN_EPS);
    scale[c] = sc;
    shift[c] = beta[c] - mean * sc;
}

// ---------------- final BN2 + ReLU ----------------
__global__ void apply_kernel(const float* __restrict__ H,
                             const float* __restrict__ scale, const float* __restrict__ shift,
                             float* __restrict__ out) {
    size_t i = (size_t)blockIdx.x * blockDim.x + threadIdx.x;   // float4 index
    float4 v = ((const float4*)H)[i];
    int c = (int)((i * 4) & (H2_ - 1));
    float4 o;
    o.x = fmaxf(fmaf(v.x, scale[c + 0], shift[c + 0]), 0.0f);
    o.y = fmaxf(fmaf(v.y, scale[c + 1], shift[c + 1]), 0.0f);
    o.z = fmaxf(fmaf(v.z, scale[c + 2], shift[c + 2]), 0.0f);
    o.w = fmaxf(fmaf(v.w, scale[c + 3], shift[c + 3]), 0.0f);
    ((float4*)out)[i] = o;
}

// ---------------- host launcher ----------------
extern "C" void kernel_launch(void* const* d_in, const int* in_sizes, int n_in,
                              void* d_out, int out_size) {
    const float* xyz1    = (const float*)d_in[0];
    const float* xyz2    = (const float*)d_in[1];
    const float* points1 = (const float*)d_in[2];
    const float* points2 = (const float*)d_in[3];
    const float* W1      = (const float*)d_in[4];
    // d_in[5] = b1 : cancels under BatchNorm (mean subtraction) -> unused
    const float* gamma1  = (const float*)d_in[6];
    const float* beta1   = (const float*)d_in[7];
    const float* W2      = (const float*)d_in[8];
    // d_in[9] = b2 : cancels under BatchNorm -> unused
    const float* gamma2  = (const float*)d_in[10];
    const float* beta2   = (const float*)d_in[11];
    float* out = (float*)d_out;

    float *px, *ph1, *ph2, *pwt1, *pwt2, *pps, *ppq, *psc1, *psh1, *psc2, *psh2;
    cudaGetSymbolAddress((void**)&px,   g_x);
    cudaGetSymbolAddress((void**)&ph1,  g_h1);
    cudaGetSymbolAddress((void**)&ph2,  g_h2);
    cudaGetSymbolAddress((void**)&pwt1, g_Wt1);
    cudaGetSymbolAddress((void**)&pwt2, g_Wt2);
    cudaGetSymbolAddress((void**)&pps,  g_psum);
    cudaGetSymbolAddress((void**)&ppq,  g_psq);
    cudaGetSymbolAddress((void**)&psc1, g_scale1);
    cudaGetSymbolAddress((void**)&psh1, g_shift1);
    cudaGetSymbolAddress((void**)&psc2, g_scale2);
    cudaGetSymbolAddress((void**)&psh2, g_shift2);

    // weight transposes (tiny)
    transpose_kernel<<<(H1_ * INCH_ + 255) / 256, 256>>>(W1, pwt1, H1_, INCH_);
    transpose_kernel<<<(H2_ * H1_  + 255) / 256, 256>>>(W2, pwt2, H2_, H1_);

    // 3-NN + interpolate + concat -> g_x [M,384]
    {
        dim3 grid(N1_ / QPB, B_);
        knn_interp_kernel<<<grid, KNN_T>>>(xyz1, xyz2, points1, points2, px);
    }

    // GEMM1: g_h1 = g_x @ W1^T   (bias dropped: cancels in BN)
    {
        dim3 grid(M_ / 128, H1_ / 128);
        gemm_kernel<INCH_, H1_, false><<<grid, 256>>>(px, pwt1, nullptr, nullptr, ph1);
    }

    // BN1 stats -> scale1/shift1
    stats_kernel<H1_><<<STAT_BLKS, H1_>>>(ph1, pps, ppq);
    reduce_kernel<H1_><<<1, H1_>>>(pps, ppq, gamma1, beta1, psc1, psh1);

    // GEMM2 with fused BN1+ReLU on the A operand: g_h2 = relu(bn1(g_h1)) @ W2^T
    {
        dim3 grid(M_ / 128, H2_ / 128);
        gemm_kernel<H1_, H2_, true><<<grid, 256>>>(ph1, pwt2, psc1, psh1, ph2);
    }

    // BN2 stats -> scale2/shift2
    stats_kernel<H2_><<<STAT_BLKS, H2_>>>(ph2, pps, ppq);
    reduce_kernel<H2_><<<1, H2_>>>(pps, ppq, gamma2, beta2, psc2, psh2);

    // final BN2 + ReLU -> d_out [M,128]
    {
        size_t n4 = (size_t)M_ * H2_ / 4;
        apply_kernel<<<(unsigned)(n4 / 256), 256>>>(ph2, psc2, psh2, out);
    }
}

// round 8
// speedup vs baseline: 2.3123x; 1.5069x over previous
#include <cuda_runtime.h>
#include <cstdint>

#define B_    8
#define N1_   16384
#define N2_   2048
#define C1_   128
#define C2_   256
#define INCH_ 384
#define H1_   256
#define H2_   128
#define M_    (B_ * N1_)            // 131072 rows
#define STAT_ROWS 256
#define STAT_BLKS (M_ / STAT_ROWS)  // 512
#define BN_EPS 1e-5f

// ---------------- scratch (device globals; no cudaMalloc allowed) ----------------
__device__ float g_x  [(size_t)M_ * INCH_];   // concat(points1, interp)  [M,384]
__device__ float g_h1 [(size_t)M_ * H1_];     // GEMM1 out (pre-BN)       [M,256]
__device__ float g_h2 [(size_t)M_ * H2_];     // GEMM2 out (pre-BN)       [M,128]
__device__ float g_psum[STAT_BLKS * H1_];
__device__ float g_psq [STAT_BLKS * H1_];
__device__ float g_scale1[H1_], g_shift1[H1_];
__device__ float g_scale2[H2_], g_shift2[H2_];

// ---------------- 3-NN + interpolation + concat ----------------
#define QPT 4
#define KNN_T 128
#define QPB (QPT * KNN_T)   // 512 queries per block

__global__ __launch_bounds__(KNN_T)
void knn_interp_kernel(const float* __restrict__ xyz1, const float* __restrict__ xyz2,
                       const float* __restrict__ points1, const float* __restrict__ points2,
                       float* __restrict__ x_out) {
    __shared__ float sx[N2_], sy[N2_], sz[N2_];
    __shared__ int   s_idx[QPB][3];
    __shared__ float s_w  [QPB][3];

    const int b   = blockIdx.y;
    const int q0  = blockIdx.x * QPB;
    const int tid = threadIdx.x;

    const float* x2 = xyz2 + (size_t)b * N2_ * 3;
    for (int j = tid; j < N2_; j += KNN_T) {
        float3 v = ((const float3*)x2)[j];
        sx[j] = v.x; sy[j] = v.y; sz[j] = v.z;
    }
    __syncthreads();

    float px[QPT], py[QPT], pz[QPT];
    float d0[QPT], d1[QPT], d2[QPT];
    int   i0[QPT], i1[QPT], i2[QPT];
#pragma unroll
    for (int i = 0; i < QPT; i++) {
        const int q = q0 + i * KNN_T + tid;
        float3 p = ((const float3*)(xyz1 + (size_t)b * N1_ * 3))[q];
        px[i] = p.x; py[i] = p.y; pz[i] = p.z;
        d0[i] = 1e30f; d1[i] = 1e30f; d2[i] = 1e30f;
        i0[i] = 0; i1[i] = 0; i2[i] = 0;
    }

#pragma unroll 4
    for (int j = 0; j < N2_; j++) {
        const float cx = sx[j], cy = sy[j], cz = sz[j];
#pragma unroll
        for (int i = 0; i < QPT; i++) {
            float dx = px[i] - cx;
            float dy = py[i] - cy;
            float dz = pz[i] - cz;
            float d  = fmaf(dx, dx, fmaf(dy, dy, dz * dz));
            if (d < d2[i]) {
                if (d < d0[i])      { d2[i]=d1[i]; i2[i]=i1[i]; d1[i]=d0[i]; i1[i]=i0[i]; d0[i]=d; i0[i]=j; }
                else if (d < d1[i]) { d2[i]=d1[i]; i2[i]=i1[i]; d1[i]=d;  i1[i]=j; }
                else                { d2[i]=d;  i2[i]=j; }
            }
        }
    }

#pragma unroll
    for (int i = 0; i < QPT; i++) {
        float a0 = 1.0f / fmaxf(d0[i], 1e-10f);
        float a1 = 1.0f / fmaxf(d1[i], 1e-10f);
        float a2 = 1.0f / fmaxf(d2[i], 1e-10f);
        float inv = 1.0f / fmaxf(a0 + a1 + a2, 1e-8f);
        const int lq = i * KNN_T + tid;
        s_idx[lq][0] = i0[i]; s_idx[lq][1] = i1[i]; s_idx[lq][2] = i2[i];
        s_w[lq][0] = a0 * inv; s_w[lq][1] = a1 * inv; s_w[lq][2] = a2 * inv;
    }
    __syncthreads();

    const int warp = tid >> 5, lane = tid & 31;
    const float* p2  = points2 + (size_t)b * N2_ * C2_;
    const float* p1b = points1 + ((size_t)b * N1_ + q0) * C1_;
    float* xb = x_out + ((size_t)b * N1_ + q0) * INCH_;

    for (int lq = warp; lq < QPB; lq += 4) {
        const int   j0 = s_idx[lq][0], j1 = s_idx[lq][1], j2 = s_idx[lq][2];
        const float a0 = s_w[lq][0],   a1 = s_w[lq][1],   a2 = s_w[lq][2];
        const float* r0 = p2 + (size_t)j0 * C2_;
        const float* r1 = p2 + (size_t)j1 * C2_;
        const float* r2 = p2 + (size_t)j2 * C2_;
        float* xrow = xb + (size_t)lq * INCH_;
#pragma unroll
        for (int c = lane; c < C2_; c += 32)
            xrow[C1_ + c] = fmaf(a0, r0[c], fmaf(a1, r1[c], a2 * r2[c]));
        const float* pr = p1b + (size_t)lq * C1_;
#pragma unroll
        for (int c = lane; c < C1_; c += 32)
            xrow[c] = pr[c];
    }
}

// ---------------- tf32 tensor-core GEMM ----------------
// C[M,N] = op(A)[M,K] @ W[N,K]^T   (W consumed n-major directly, no transpose)
// Block 128x128, 8 warps (4M x 2N), warp tile 32x64, BK=16 single-buffered.
// Fragments via ldmatrix.m8n8.x4.b16: an 8x4-float tile == one 8x8-b16 unit,
// and the non-trans lane map (row=lane>>2,col=lane&3) IS the tf32 frag map.
// Smem rows padded 16->20 floats (80B stride) => ldmatrix row addresses hit
// 8 distinct bank groups => conflict-free LDSM.
// Optional fused BN+ReLU on A (per-K-channel scale/shift then max(.,0)).

__device__ __forceinline__ uint32_t f2tf32(float x) {
    uint32_t u;
    asm("cvt.rna.tf32.f32 %0, %1;" : "=r"(u) : "f"(x));
    return u;
}

#define LDSM4(R, ADDR)                                                          \
    asm volatile("ldmatrix.sync.aligned.m8n8.x4.shared.b16 {%0,%1,%2,%3}, [%4];"\
                 : "=r"(R[0]), "=r"(R[1]), "=r"(R[2]), "=r"(R[3]) : "r"(ADDR))

#define MMA_TF32(D, A, B0, B1)                                                  \
    asm volatile("mma.sync.aligned.m16n8k8.row.col.f32.tf32.tf32.f32 "          \
                 "{%0,%1,%2,%3},{%4,%5,%6,%7},{%8,%9},{%0,%1,%2,%3};"           \
                 : "+f"(D[0]), "+f"(D[1]), "+f"(D[2]), "+f"(D[3])               \
                 : "r"(A[0]), "r"(A[1]), "r"(A[2]), "r"(A[3]), "r"(B0), "r"(B1))

template <int K, int N, bool BN>
__global__ __launch_bounds__(256, 2)
void gemm_tc(const float* __restrict__ A, const float* __restrict__ W,
             const float* __restrict__ scale, const float* __restrict__ shift,
             float* __restrict__ C) {
    __shared__ uint32_t As[128][20];   // [m][k16 padded to 20]
    __shared__ uint32_t Bs[128][20];   // [n][k16 padded to 20]

    const int tid  = threadIdx.x;
    const int lane = tid & 31;
    const int warp = tid >> 5;
    const int wm   = warp & 3;         // 0..3 -> M offset wm*32
    const int wn   = warp >> 2;        // 0..1 -> N offset wn*64
    const int m0   = blockIdx.x * 128;
    const int n0   = blockIdx.y * 128;

    // staging: thread -> one row (A: m, B: n), 8 consecutive k
    const int sr = tid & 127;
    const int sc = (tid >> 7) * 8;     // 0 or 8
    const float* Ap = A + (size_t)(m0 + sr) * K + sc;
    const float* Wp = W + (size_t)(n0 + sr) * K + sc;

    // ldmatrix per-lane addresses. sel = lane>>3 picks the 8x4 sub-matrix.
    const int r8  = lane & 7;
    const int sel = lane >> 3;
    uint32_t as_base = (uint32_t)__cvta_generic_to_shared(&As[0][0]);
    uint32_t bs_base = (uint32_t)__cvta_generic_to_shared(&Bs[0][0]);
    // A: sel -> (m += (sel&1)*8, k += (sel&2)*2) : a0,a1,a2,a3
    uint32_t a_addr[2][2];
#pragma unroll
    for (int mt = 0; mt < 2; mt++)
#pragma unroll
        for (int c = 0; c < 2; c++)
            a_addr[mt][c] = as_base +
                (((wm * 32 + mt * 16) + r8 + (sel & 1) * 8) * 20 + c * 8 + (sel & 2) * 2) * 4;
    // B: sel -> (n += (sel>>1)*8, k += (sel&1)*4) : b0(t0),b1(t0),b0(t1),b1(t1)
    uint32_t b_addr[4][2];
#pragma unroll
    for (int p = 0; p < 4; p++)
#pragma unroll
        for (int c = 0; c < 2; c++)
            b_addr[p][c] = bs_base +
                (((wn * 64 + p * 16) + r8 + (sel >> 1) * 8) * 20 + c * 8 + (sel & 1) * 4) * 4;

    float acc[2][8][4];
#pragma unroll
    for (int mt = 0; mt < 2; mt++)
#pragma unroll
        for (int nt = 0; nt < 8; nt++)
#pragma unroll
            for (int i = 0; i < 4; i++) acc[mt][nt][i] = 0.0f;

#pragma unroll 1
    for (int k0 = 0; k0 < K; k0 += 16) {
        // gmem loads first (overlap with previous tile's compute)
        float4 av0 = *(const float4*)(Ap + k0);
        float4 av1 = *(const float4*)(Ap + k0 + 4);
        float4 bv0 = *(const float4*)(Wp + k0);
        float4 bv1 = *(const float4*)(Wp + k0 + 4);
        if (BN) {
            const float* s = scale + k0 + sc; const float* h = shift + k0 + sc;
            av0.x = fmaxf(fmaf(av0.x, s[0], h[0]), 0.f);
            av0.y = fmaxf(fmaf(av0.y, s[1], h[1]), 0.f);
            av0.z = fmaxf(fmaf(av0.z, s[2], h[2]), 0.f);
            av0.w = fmaxf(fmaf(av0.w, s[3], h[3]), 0.f);
            av1.x = fmaxf(fmaf(av1.x, s[4], h[4]), 0.f);
            av1.y = fmaxf(fmaf(av1.y, s[5], h[5]), 0.f);
            av1.z = fmaxf(fmaf(av1.z, s[6], h[6]), 0.f);
            av1.w = fmaxf(fmaf(av1.w, s[7], h[7]), 0.f);
        }
        __syncthreads();   // previous tile fully consumed
        {
            uint4 ua = { f2tf32(av0.x), f2tf32(av0.y), f2tf32(av0.z), f2tf32(av0.w) };
            uint4 ub = { f2tf32(av1.x), f2tf32(av1.y), f2tf32(av1.z), f2tf32(av1.w) };
            *(uint4*)&As[sr][sc]     = ua;
            *(uint4*)&As[sr][sc + 4] = ub;
            uint4 uc = { f2tf32(bv0.x), f2tf32(bv0.y), f2tf32(bv0.z), f2tf32(bv0.w) };
            uint4 ud = { f2tf32(bv1.x), f2tf32(bv1.y), f2tf32(bv1.z), f2tf32(bv1.w) };
            *(uint4*)&Bs[sr][sc]     = uc;
            *(uint4*)&Bs[sr][sc + 4] = ud;
        }
        __syncthreads();

#pragma unroll
        for (int c = 0; c < 2; c++) {
            uint32_t af[2][4];
            LDSM4(af[0], a_addr[0][c]);
            LDSM4(af[1], a_addr[1][c]);
            uint32_t bf[4][4];
#pragma unroll
            for (int p = 0; p < 4; p++) LDSM4(bf[p], b_addr[p][c]);
#pragma unroll
            for (int mt = 0; mt < 2; mt++)
#pragma unroll
                for (int nt = 0; nt < 8; nt++) {
                    const int p = nt >> 1, wh = nt & 1;
                    MMA_TF32(acc[mt][nt], af[mt], bf[p][wh * 2], bf[p][wh * 2 + 1]);
                }
        }
    }

    // epilogue: c0,c1 -> (row, col..col+1); c2,c3 -> (row+8, ...)
    const int rr = lane >> 2;
    const int cc = (lane & 3) * 2;
#pragma unroll
    for (int mt = 0; mt < 2; mt++)
#pragma unroll
        for (int nt = 0; nt < 8; nt++) {
            const int row = m0 + wm * 32 + mt * 16 + rr;
            const int col = n0 + wn * 64 + nt * 8 + cc;
            float2 v0 = { acc[mt][nt][0], acc[mt][nt][1] };
            float2 v1 = { acc[mt][nt][2], acc[mt][nt][3] };
            *(float2*)&C[(size_t)row * N + col]       = v0;
            *(float2*)&C[(size_t)(row + 8) * N + col] = v1;
        }
}

// ---------------- BN stats: per-block partial sums (deterministic) ----------------
template <int C>
__global__ void stats_kernel(const float* __restrict__ H,
                             float* __restrict__ psum, float* __restrict__ psq) {
    const int c = threadIdx.x;
    size_t base = (size_t)blockIdx.x * STAT_ROWS * C + c;
    float s = 0.0f, s2 = 0.0f;
#pragma unroll 4
    for (int r = 0; r < STAT_ROWS; r++) {
        float v = H[base + (size_t)r * C];
        s += v;
        s2 = fmaf(v, v, s2);
    }
    psum[blockIdx.x * C + c] = s;
    psq [blockIdx.x * C + c] = s2;
}

template <int C>
__global__ void reduce_kernel(const float* __restrict__ psum, const float* __restrict__ psq,
                              const float* __restrict__ gamma, const float* __restrict__ beta,
                              float* __restrict__ scale, float* __restrict__ shift) {
    const int c = threadIdx.x;
    float s = 0.0f, s2 = 0.0f;
    for (int i = 0; i < STAT_BLKS; i++) {
        s  += psum[i * C + c];
        s2 += psq [i * C + c];
    }
    const float invn = 1.0f / (float)M_;
    float mean = s * invn;
    float var  = s2 * invn - mean * mean;
    float sc = gamma[c] * rsqrtf(var + BN_EPS);
    scale[c] = sc;
    shift[c] = beta[c] - mean * sc;
}

// ---------------- final BN2 + ReLU ----------------
__global__ void apply_kernel(const float* __restrict__ H,
                             const float* __restrict__ scale, const float* __restrict__ shift,
                             float* __restrict__ out) {
    size_t i = (size_t)blockIdx.x * blockDim.x + threadIdx.x;
    float4 v = ((const float4*)H)[i];
    int c = (int)((i * 4) & (H2_ - 1));
    float4 o;
    o.x = fmaxf(fmaf(v.x, scale[c + 0], shift[c + 0]), 0.0f);
    o.y = fmaxf(fmaf(v.y, scale[c + 1], shift[c + 1]), 0.0f);
    o.z = fmaxf(fmaf(v.z, scale[c + 2], shift[c + 2]), 0.0f);
    o.w = fmaxf(fmaf(v.w, scale[c + 3], shift[c + 3]), 0.0f);
    ((float4*)out)[i] = o;
}

// ---------------- host launcher ----------------
extern "C" void kernel_launch(void* const* d_in, const int* in_sizes, int n_in,
                              void* d_out, int out_size) {
    const float* xyz1    = (const float*)d_in[0];
    const float* xyz2    = (const float*)d_in[1];
    const float* points1 = (const float*)d_in[2];
    const float* points2 = (const float*)d_in[3];
    const float* W1      = (const float*)d_in[4];   // [256 out][384 in] = n-major
    // d_in[5] = b1 : cancels under BatchNorm -> unused
    const float* gamma1  = (const float*)d_in[6];
    const float* beta1   = (const float*)d_in[7];
    const float* W2      = (const float*)d_in[8];   // [128 out][256 in] = n-major
    // d_in[9] = b2 : cancels under BatchNorm -> unused
    const float* gamma2  = (const float*)d_in[10];
    const float* beta2   = (const float*)d_in[11];
    float* out = (float*)d_out;

    float *px, *ph1, *ph2, *pps, *ppq, *psc1, *psh1, *psc2, *psh2;
    cudaGetSymbolAddress((void**)&px,   g_x);
    cudaGetSymbolAddress((void**)&ph1,  g_h1);
    cudaGetSymbolAddress((void**)&ph2,  g_h2);
    cudaGetSymbolAddress((void**)&pps,  g_psum);
    cudaGetSymbolAddress((void**)&ppq,  g_psq);
    cudaGetSymbolAddress((void**)&psc1, g_scale1);
    cudaGetSymbolAddress((void**)&psh1, g_shift1);
    cudaGetSymbolAddress((void**)&psc2, g_scale2);
    cudaGetSymbolAddress((void**)&psh2, g_shift2);

    // 3-NN + interpolate + concat -> g_x [M,384]
    {
        dim3 grid(N1_ / QPB, B_);
        knn_interp_kernel<<<grid, KNN_T>>>(xyz1, xyz2, points1, points2, px);
    }

    // GEMM1 (tf32 TC): g_h1 = g_x @ W1^T
    {
        dim3 grid(M_ / 128, H1_ / 128);
        gemm_tc<INCH_, H1_, false><<<grid, 256>>>(px, W1, nullptr, nullptr, ph1);
    }

    // BN1 stats -> scale1/shift1
    stats_kernel<H1_><<<STAT_BLKS, H1_>>>(ph1, pps, ppq);
    reduce_kernel<H1_><<<1, H1_>>>(pps, ppq, gamma1, beta1, psc1, psh1);

    // GEMM2 (tf32 TC) with fused BN1+ReLU on A: g_h2 = relu(bn1(g_h1)) @ W2^T
    {
        dim3 grid(M_ / 128, H2_ / 128);
        gemm_tc<H1_, H2_, true><<<grid, 256>>>(ph1, W2, psc1, psh1, ph2);
    }

    // BN2 stats -> scale2/shift2
    stats_kernel<H2_><<<STAT_BLKS, H2_>>>(ph2, pps, ppq);
    reduce_kernel<H2_><<<1, H2_>>>(pps, ppq, gamma2, beta2, psc2, psh2);

    // final BN2 + ReLU -> d_out [M,128]
    {
        size_t n4 = (size_t)M_ * H2_ / 4;
        apply_kernel<<<(unsigned)(n4 / 256), 256>>>(ph2, psc2, psh2, out);
    }
}

// round 9
// speedup vs baseline: 2.5477x; 1.1018x over previous
#include <cuda_runtime.h>
#include <cstdint>

#define B_    8
#define N1_   16384
#define N2_   2048
#define C1_   128
#define C2_   256
#define INCH_ 384
#define H1_   256
#define H2_   128
#define M_    (B_ * N1_)            // 131072 rows
#define MT_   (M_ / 128)            // 1024 M-tiles (partial-stat blocks)
#define BN_EPS 1e-5f

// ---------------- scratch (device globals; no cudaMalloc allowed) ----------------
__device__ float g_x  [(size_t)M_ * INCH_];   // concat(points1, interp)  [M,384]
__device__ float g_h1 [(size_t)M_ * H1_];     // GEMM1 out (pre-BN)       [M,256]
__device__ float g_h2 [(size_t)M_ * H2_];     // GEMM2 out (pre-BN)       [M,128]
__device__ float g_psum[(size_t)MT_ * H1_];   // per-M-tile per-channel partial sums
__device__ float g_psq [(size_t)MT_ * H1_];
__device__ float g_scale1[H1_], g_shift1[H1_];
__device__ float g_scale2[H2_], g_shift2[H2_];

// ---------------- 3-NN + interpolation + concat ----------------
#define QPT 4
#define KNN_T 128
#define QPB (QPT * KNN_T)   // 512 queries per block

__global__ __launch_bounds__(KNN_T)
void knn_interp_kernel(const float* __restrict__ xyz1, const float* __restrict__ xyz2,
                       const float* __restrict__ points1, const float* __restrict__ points2,
                       float* __restrict__ x_out) {
    __shared__ float sx[N2_], sy[N2_], sz[N2_];
    __shared__ int   s_idx[QPB][3];
    __shared__ float s_w  [QPB][3];

    const int b   = blockIdx.y;
    const int q0  = blockIdx.x * QPB;
    const int tid = threadIdx.x;

    const float* x2 = xyz2 + (size_t)b * N2_ * 3;
    for (int j = tid; j < N2_; j += KNN_T) {
        float3 v = ((const float3*)x2)[j];
        sx[j] = v.x; sy[j] = v.y; sz[j] = v.z;
    }
    __syncthreads();

    float px[QPT], py[QPT], pz[QPT];
    float d0[QPT], d1[QPT], d2[QPT];
    int   i0[QPT], i1[QPT], i2[QPT];
#pragma unroll
    for (int i = 0; i < QPT; i++) {
        const int q = q0 + i * KNN_T + tid;
        float3 p = ((const float3*)(xyz1 + (size_t)b * N1_ * 3))[q];
        px[i] = p.x; py[i] = p.y; pz[i] = p.z;
        d0[i] = 1e30f; d1[i] = 1e30f; d2[i] = 1e30f;
        i0[i] = 0; i1[i] = 0; i2[i] = 0;
    }

#pragma unroll 4
    for (int j = 0; j < N2_; j++) {
        const float cx = sx[j], cy = sy[j], cz = sz[j];
#pragma unroll
        for (int i = 0; i < QPT; i++) {
            float dx = px[i] - cx;
            float dy = py[i] - cy;
            float dz = pz[i] - cz;
            float d  = fmaf(dx, dx, fmaf(dy, dy, dz * dz));
            if (d < d2[i]) {
                if (d < d0[i])      { d2[i]=d1[i]; i2[i]=i1[i]; d1[i]=d0[i]; i1[i]=i0[i]; d0[i]=d; i0[i]=j; }
                else if (d < d1[i]) { d2[i]=d1[i]; i2[i]=i1[i]; d1[i]=d;  i1[i]=j; }
                else                { d2[i]=d;  i2[i]=j; }
            }
        }
    }

#pragma unroll
    for (int i = 0; i < QPT; i++) {
        float a0 = 1.0f / fmaxf(d0[i], 1e-10f);
        float a1 = 1.0f / fmaxf(d1[i], 1e-10f);
        float a2 = 1.0f / fmaxf(d2[i], 1e-10f);
        float inv = 1.0f / fmaxf(a0 + a1 + a2, 1e-8f);
        const int lq = i * KNN_T + tid;
        s_idx[lq][0] = i0[i]; s_idx[lq][1] = i1[i]; s_idx[lq][2] = i2[i];
        s_w[lq][0] = a0 * inv; s_w[lq][1] = a1 * inv; s_w[lq][2] = a2 * inv;
    }
    __syncthreads();

    const int warp = tid >> 5, lane = tid & 31;
    const float* p2  = points2 + (size_t)b * N2_ * C2_;
    const float* p1b = points1 + ((size_t)b * N1_ + q0) * C1_;
    float* xb = x_out + ((size_t)b * N1_ + q0) * INCH_;

    for (int lq = warp; lq < QPB; lq += 4) {
        const int   j0 = s_idx[lq][0], j1 = s_idx[lq][1], j2 = s_idx[lq][2];
        const float a0 = s_w[lq][0],   a1 = s_w[lq][1],   a2 = s_w[lq][2];
        const float* r0 = p2 + (size_t)j0 * C2_;
        const float* r1 = p2 + (size_t)j1 * C2_;
        const float* r2 = p2 + (size_t)j2 * C2_;
        float* xrow = xb + (size_t)lq * INCH_;
#pragma unroll
        for (int c = lane; c < C2_; c += 32)
            xrow[C1_ + c] = fmaf(a0, r0[c], fmaf(a1, r1[c], a2 * r2[c]));
        const float* pr = p1b + (size_t)lq * C1_;
#pragma unroll
        for (int c = lane; c < C1_; c += 32)
            xrow[c] = pr[c];
    }
}

// ---------------- tf32 tensor-core GEMM with fused per-block BN stats ----------------
// C[M,N] = op(A)[M,K] @ W[N,K]^T. Block 128x128, 8 warps (4M x 2N), BK=16.
// Epilogue computes deterministic per-column sum / sum-of-squares of the
// 128x128 output tile (smem tree, fixed order) -> psum/psq[blockIdx.x][col].

__device__ __forceinline__ uint32_t f2tf32(float x) {
    uint32_t u;
    asm("cvt.rna.tf32.f32 %0, %1;" : "=r"(u) : "f"(x));
    return u;
}

#define LDSM4(R, ADDR)                                                          \
    asm volatile("ldmatrix.sync.aligned.m8n8.x4.shared.b16 {%0,%1,%2,%3}, [%4];"\
                 : "=r"(R[0]), "=r"(R[1]), "=r"(R[2]), "=r"(R[3]) : "r"(ADDR))

#define MMA_TF32(D, A, B0, B1)                                                  \
    asm volatile("mma.sync.aligned.m16n8k8.row.col.f32.tf32.tf32.f32 "          \
                 "{%0,%1,%2,%3},{%4,%5,%6,%7},{%8,%9},{%0,%1,%2,%3};"           \
                 : "+f"(D[0]), "+f"(D[1]), "+f"(D[2]), "+f"(D[3])               \
                 : "r"(A[0]), "r"(A[1]), "r"(A[2]), "r"(A[3]), "r"(B0), "r"(B1))

union GemmSmem {
    struct { uint32_t As[128][20]; uint32_t Bs[128][20]; } t;   // 20.5 KB
    struct { float s[128][33]; float q[128][33]; } r;           // 33.8 KB
};

template <int K, int N, bool BN>
__global__ __launch_bounds__(256, 2)
void gemm_tc(const float* __restrict__ A, const float* __restrict__ W,
             const float* __restrict__ scale, const float* __restrict__ shift,
             float* __restrict__ C,
             float* __restrict__ psum, float* __restrict__ psq) {
    __shared__ GemmSmem sm;

    const int tid  = threadIdx.x;
    const int lane = tid & 31;
    const int warp = tid >> 5;
    const int wm   = warp & 3;
    const int wn   = warp >> 2;
    const int m0   = blockIdx.x * 128;
    const int n0   = blockIdx.y * 128;

    const int sr = tid & 127;
    const int sc = (tid >> 7) * 8;
    const float* Ap = A + (size_t)(m0 + sr) * K + sc;
    const float* Wp = W + (size_t)(n0 + sr) * K + sc;

    const int r8  = lane & 7;
    const int sel = lane >> 3;
    uint32_t as_base = (uint32_t)__cvta_generic_to_shared(&sm.t.As[0][0]);
    uint32_t bs_base = (uint32_t)__cvta_generic_to_shared(&sm.t.Bs[0][0]);
    uint32_t a_addr[2][2];
#pragma unroll
    for (int mt = 0; mt < 2; mt++)
#pragma unroll
        for (int c = 0; c < 2; c++)
            a_addr[mt][c] = as_base +
                (((wm * 32 + mt * 16) + r8 + (sel & 1) * 8) * 20 + c * 8 + (sel & 2) * 2) * 4;
    uint32_t b_addr[4][2];
#pragma unroll
    for (int p = 0; p < 4; p++)
#pragma unroll
        for (int c = 0; c < 2; c++)
            b_addr[p][c] = bs_base +
                (((wn * 64 + p * 16) + r8 + (sel >> 1) * 8) * 20 + c * 8 + (sel & 1) * 4) * 4;

    float acc[2][8][4];
#pragma unroll
    for (int mt = 0; mt < 2; mt++)
#pragma unroll
        for (int nt = 0; nt < 8; nt++)
#pragma unroll
            for (int i = 0; i < 4; i++) acc[mt][nt][i] = 0.0f;

#pragma unroll 1
    for (int k0 = 0; k0 < K; k0 += 16) {
        float4 av0 = *(const float4*)(Ap + k0);
        float4 av1 = *(const float4*)(Ap + k0 + 4);
        float4 bv0 = *(const float4*)(Wp + k0);
        float4 bv1 = *(const float4*)(Wp + k0 + 4);
        if (BN) {
            const float* s = scale + k0 + sc; const float* h = shift + k0 + sc;
            av0.x = fmaxf(fmaf(av0.x, s[0], h[0]), 0.f);
            av0.y = fmaxf(fmaf(av0.y, s[1], h[1]), 0.f);
            av0.z = fmaxf(fmaf(av0.z, s[2], h[2]), 0.f);
            av0.w = fmaxf(fmaf(av0.w, s[3], h[3]), 0.f);
            av1.x = fmaxf(fmaf(av1.x, s[4], h[4]), 0.f);
            av1.y = fmaxf(fmaf(av1.y, s[5], h[5]), 0.f);
            av1.z = fmaxf(fmaf(av1.z, s[6], h[6]), 0.f);
            av1.w = fmaxf(fmaf(av1.w, s[7], h[7]), 0.f);
        }
        __syncthreads();
        {
            uint4 ua = { f2tf32(av0.x), f2tf32(av0.y), f2tf32(av0.z), f2tf32(av0.w) };
            uint4 ub = { f2tf32(av1.x), f2tf32(av1.y), f2tf32(av1.z), f2tf32(av1.w) };
            *(uint4*)&sm.t.As[sr][sc]     = ua;
            *(uint4*)&sm.t.As[sr][sc + 4] = ub;
            uint4 uc = { f2tf32(bv0.x), f2tf32(bv0.y), f2tf32(bv0.z), f2tf32(bv0.w) };
            uint4 ud = { f2tf32(bv1.x), f2tf32(bv1.y), f2tf32(bv1.z), f2tf32(bv1.w) };
            *(uint4*)&sm.t.Bs[sr][sc]     = uc;
            *(uint4*)&sm.t.Bs[sr][sc + 4] = ud;
        }
        __syncthreads();

#pragma unroll
        for (int c = 0; c < 2; c++) {
            uint32_t af[2][4];
            LDSM4(af[0], a_addr[0][c]);
            LDSM4(af[1], a_addr[1][c]);
            uint32_t bf[4][4];
#pragma unroll
            for (int p = 0; p < 4; p++) LDSM4(bf[p], b_addr[p][c]);
#pragma unroll
            for (int mt = 0; mt < 2; mt++)
#pragma unroll
                for (int nt = 0; nt < 8; nt++) {
                    const int p = nt >> 1, wh = nt & 1;
                    MMA_TF32(acc[mt][nt], af[mt], bf[p][wh * 2], bf[p][wh * 2 + 1]);
                }
        }
    }

    // ---- write C tile ----
    const int rr = lane >> 2;
    const int cc = (lane & 3) * 2;
#pragma unroll
    for (int mt = 0; mt < 2; mt++)
#pragma unroll
        for (int nt = 0; nt < 8; nt++) {
            const int row = m0 + wm * 32 + mt * 16 + rr;
            const int col = n0 + wn * 64 + nt * 8 + cc;
            float2 v0 = { acc[mt][nt][0], acc[mt][nt][1] };
            float2 v1 = { acc[mt][nt][2], acc[mt][nt][3] };
            *(float2*)&C[(size_t)row * N + col]       = v0;
            *(float2*)&C[(size_t)(row + 8) * N + col] = v1;
        }

    // ---- fused per-block BN stats (deterministic fixed-order reduction) ----
    __syncthreads();   // tile buffers done; safe to reuse union as reduction space
    const int contrib = wm * 8 + rr;   // 0..31 unique per column
#pragma unroll
    for (int nt = 0; nt < 8; nt++)
#pragma unroll
        for (int d = 0; d < 2; d++) {
            const int colL = wn * 64 + nt * 8 + cc + d;
            float s = 0.0f, q = 0.0f;
#pragma unroll
            for (int mt = 0; mt < 2; mt++) {
                float v0 = acc[mt][nt][d];
                float v1 = acc[mt][nt][d + 2];
                s += v0 + v1;
                q += v0 * v0 + v1 * v1;
            }
            sm.r.s[colL][contrib] = s;
            sm.r.q[colL][contrib] = q;
        }
    __syncthreads();
    if (tid < 128) {
        float s = 0.0f, q = 0.0f;
#pragma unroll 8
        for (int i = 0; i < 32; i++) { s += sm.r.s[tid][i]; q += sm.r.q[tid][i]; }
        psum[(size_t)blockIdx.x * N + n0 + tid] = s;
        psq [(size_t)blockIdx.x * N + n0 + tid] = q;
    }
}

// ---------------- parallel BN reduce: one block per channel ----------------
template <int C, int PB>
__global__ void reduce_kernel(const float* __restrict__ psum, const float* __restrict__ psq,
                              const float* __restrict__ gamma, const float* __restrict__ beta,
                              float* __restrict__ scale, float* __restrict__ shift) {
    __shared__ float ss[256], sq[256];
    const int c = blockIdx.x;
    const int t = threadIdx.x;
    float s = 0.0f, q = 0.0f;
    for (int i = t; i < PB; i += 256) {
        s += psum[(size_t)i * C + c];
        q += psq [(size_t)i * C + c];
    }
    ss[t] = s; sq[t] = q;
    __syncthreads();
#pragma unroll
    for (int off = 128; off > 0; off >>= 1) {
        if (t < off) { ss[t] += ss[t + off]; sq[t] += sq[t + off]; }
        __syncthreads();
    }
    if (t == 0) {
        const float invn = 1.0f / (float)M_;
        float mean = ss[0] * invn;
        float var  = sq[0] * invn - mean * mean;
        float sc = gamma[c] * rsqrtf(var + BN_EPS);
        scale[c] = sc;
        shift[c] = beta[c] - mean * sc;
    }
}

// ---------------- final BN2 + ReLU ----------------
__global__ void apply_kernel(const float* __restrict__ H,
                             const float* __restrict__ scale, const float* __restrict__ shift,
                             float* __restrict__ out) {
    size_t i = (size_t)blockIdx.x * blockDim.x + threadIdx.x;
    float4 v = ((const float4*)H)[i];
    int c = (int)((i * 4) & (H2_ - 1));
    float4 o;
    o.x = fmaxf(fmaf(v.x, scale[c + 0], shift[c + 0]), 0.0f);
    o.y = fmaxf(fmaf(v.y, scale[c + 1], shift[c + 1]), 0.0f);
    o.z = fmaxf(fmaf(v.z, scale[c + 2], shift[c + 2]), 0.0f);
    o.w = fmaxf(fmaf(v.w, scale[c + 3], shift[c + 3]), 0.0f);
    ((float4*)out)[i] = o;
}

// ---------------- host launcher ----------------
extern "C" void kernel_launch(void* const* d_in, const int* in_sizes, int n_in,
                              void* d_out, int out_size) {
    const float* xyz1    = (const float*)d_in[0];
    const float* xyz2    = (const float*)d_in[1];
    const float* points1 = (const float*)d_in[2];
    const float* points2 = (const float*)d_in[3];
    const float* W1      = (const float*)d_in[4];   // [256 out][384 in] = n-major
    // d_in[5] = b1 : cancels under BatchNorm -> unused
    const float* gamma1  = (const float*)d_in[6];
    const float* beta1   = (const float*)d_in[7];
    const float* W2      = (const float*)d_in[8];   // [128 out][256 in] = n-major
    // d_in[9] = b2 : cancels under BatchNorm -> unused
    const float* gamma2  = (const float*)d_in[10];
    const float* beta2   = (const float*)d_in[11];
    float* out = (float*)d_out;

    float *px, *ph1, *ph2, *pps, *ppq, *psc1, *psh1, *psc2, *psh2;
    cudaGetSymbolAddress((void**)&px,   g_x);
    cudaGetSymbolAddress((void**)&ph1,  g_h1);
    cudaGetSymbolAddress((void**)&ph2,  g_h2);
    cudaGetSymbolAddress((void**)&pps,  g_psum);
    cudaGetSymbolAddress((void**)&ppq,  g_psq);
    cudaGetSymbolAddress((void**)&psc1, g_scale1);
    cudaGetSymbolAddress((void**)&psh1, g_shift1);
    cudaGetSymbolAddress((void**)&psc2, g_scale2);
    cudaGetSymbolAddress((void**)&psh2, g_shift2);

    // 3-NN + interpolate + concat -> g_x [M,384]
    {
        dim3 grid(N1_ / QPB, B_);
        knn_interp_kernel<<<grid, KNN_T>>>(xyz1, xyz2, points1, points2, px);
    }

    // GEMM1 (tf32 TC) + fused BN1 partial stats
    {
        dim3 grid(MT_, H1_ / 128);
        gemm_tc<INCH_, H1_, false><<<grid, 256>>>(px, W1, nullptr, nullptr, ph1, pps, ppq);
    }
    reduce_kernel<H1_, MT_><<<H1_, 256>>>(pps, ppq, gamma1, beta1, psc1, psh1);

    // GEMM2 (tf32 TC) with fused BN1+ReLU on A + fused BN2 partial stats
    {
        dim3 grid(MT_, H2_ / 128);
        gemm_tc<H1_, H2_, true><<<grid, 256>>>(ph1, W2, psc1, psh1, ph2, pps, ppq);
    }
    reduce_kernel<H2_, MT_><<<H2_, 256>>>(pps, ppq, gamma2, beta2, psc2, psh2);

    // final BN2 + ReLU -> d_out [M,128]
    {
        size_t n4 = (size_t)M_ * H2_ / 4;
        apply_kernel<<<(unsigned)(n4 / 256), 256>>>(ph2, psc2, psh2, out);
    }
}

// round 10
// speedup vs baseline: 2.6759x; 1.0503x over previous
#include <cuda_runtime.h>
#include <cstdint>

#define B_    8
#define N1_   16384
#define N2_   2048
#define C1_   128
#define C2_   256
#define INCH_ 384
#define H1_   256
#define H2_   128
#define M_    (B_ * N1_)            // 131072 rows
#define MT_   (M_ / 128)            // 1024 M-tiles (partial-stat blocks)
#define BN_EPS 1e-5f

// ---------------- scratch (device globals; no cudaMalloc allowed) ----------------
__device__ float g_x  [(size_t)M_ * INCH_];   // concat(points1, interp)  [M,384]
__device__ float g_h1 [(size_t)M_ * H1_];     // GEMM1 out (pre-BN)       [M,256]
__device__ float g_h2 [(size_t)M_ * H2_];     // GEMM2 out (pre-BN)       [M,128]
__device__ float g_psum[(size_t)MT_ * H1_];   // per-M-tile per-channel partial sums
__device__ float g_psq [(size_t)MT_ * H1_];
__device__ float g_scale1[H1_], g_shift1[H1_];
__device__ float g_scale2[H2_], g_shift2[H2_];

// ---------------- 3-NN + interpolation + concat ----------------
#define QPT 4
#define KNN_T 128
#define QPB (QPT * KNN_T)   // 512 queries per block

__global__ __launch_bounds__(KNN_T)
void knn_interp_kernel(const float* __restrict__ xyz1, const float* __restrict__ xyz2,
                       const float* __restrict__ points1, const float* __restrict__ points2,
                       float* __restrict__ x_out) {
    __shared__ float sx[N2_], sy[N2_], sz[N2_];
    __shared__ int   s_idx[QPB][3];
    __shared__ float s_w  [QPB][3];

    const int b   = blockIdx.y;
    const int q0  = blockIdx.x * QPB;
    const int tid = threadIdx.x;

    const float* x2 = xyz2 + (size_t)b * N2_ * 3;
    for (int j = tid; j < N2_; j += KNN_T) {
        float3 v = ((const float3*)x2)[j];
        sx[j] = v.x; sy[j] = v.y; sz[j] = v.z;
    }
    __syncthreads();

    float px[QPT], py[QPT], pz[QPT];
    float d0[QPT], d1[QPT], d2[QPT];
    int   i0[QPT], i1[QPT], i2[QPT];
#pragma unroll
    for (int i = 0; i < QPT; i++) {
        const int q = q0 + i * KNN_T + tid;
        float3 p = ((const float3*)(xyz1 + (size_t)b * N1_ * 3))[q];
        px[i] = p.x; py[i] = p.y; pz[i] = p.z;
        d0[i] = 1e30f; d1[i] = 1e30f; d2[i] = 1e30f;
        i0[i] = 0; i1[i] = 0; i2[i] = 0;
    }

#pragma unroll 4
    for (int j = 0; j < N2_; j++) {
        const float cx = sx[j], cy = sy[j], cz = sz[j];
#pragma unroll
        for (int i = 0; i < QPT; i++) {
            float dx = px[i] - cx;
            float dy = py[i] - cy;
            float dz = pz[i] - cz;
            float d  = fmaf(dx, dx, fmaf(dy, dy, dz * dz));
            if (d < d2[i]) {
                if (d < d0[i])      { d2[i]=d1[i]; i2[i]=i1[i]; d1[i]=d0[i]; i1[i]=i0[i]; d0[i]=d; i0[i]=j; }
                else if (d < d1[i]) { d2[i]=d1[i]; i2[i]=i1[i]; d1[i]=d;  i1[i]=j; }
                else                { d2[i]=d;  i2[i]=j; }
            }
        }
    }

#pragma unroll
    for (int i = 0; i < QPT; i++) {
        float a0 = 1.0f / fmaxf(d0[i], 1e-10f);
        float a1 = 1.0f / fmaxf(d1[i], 1e-10f);
        float a2 = 1.0f / fmaxf(d2[i], 1e-10f);
        float inv = 1.0f / fmaxf(a0 + a1 + a2, 1e-8f);
        const int lq = i * KNN_T + tid;
        s_idx[lq][0] = i0[i]; s_idx[lq][1] = i1[i]; s_idx[lq][2] = i2[i];
        s_w[lq][0] = a0 * inv; s_w[lq][1] = a1 * inv; s_w[lq][2] = a2 * inv;
    }
    __syncthreads();

    const int warp = tid >> 5, lane = tid & 31;
    const float* p2  = points2 + (size_t)b * N2_ * C2_;
    const float* p1b = points1 + ((size_t)b * N1_ + q0) * C1_;
    float* xb = x_out + ((size_t)b * N1_ + q0) * INCH_;

    for (int lq = warp; lq < QPB; lq += 4) {
        const int   j0 = s_idx[lq][0], j1 = s_idx[lq][1], j2 = s_idx[lq][2];
        const float a0 = s_w[lq][0],   a1 = s_w[lq][1],   a2 = s_w[lq][2];
        const float* r0 = p2 + (size_t)j0 * C2_;
        const float* r1 = p2 + (size_t)j1 * C2_;
        const float* r2 = p2 + (size_t)j2 * C2_;
        float* xrow = xb + (size_t)lq * INCH_;
#pragma unroll
        for (int c = lane; c < C2_; c += 32)
            xrow[C1_ + c] = fmaf(a0, r0[c], fmaf(a1, r1[c], a2 * r2[c]));
        const float* pr = p1b + (size_t)lq * C1_;
#pragma unroll
        for (int c = lane; c < C1_; c += 32)
            xrow[c] = pr[c];
    }
}

// ---------------- tf32 TC GEMM: cp.async 2-stage pipeline + fused BN stats ----------------
// C[M,N] = op(A)[M,K] @ W[N,K]^T. Block 128x128, 8 warps (4M x 2N), BK=16.
// Raw fp32 staged via cp.async into double-buffered smem; tf32 convert (and
// GEMM2's BN1+ReLU) applied on fragment registers after ldmatrix.
// Epilogue: deterministic per-column sum/sum^2 partials -> psum/psq.

__device__ __forceinline__ uint32_t f2tf32(float x) {
    uint32_t u;
    asm("cvt.rna.tf32.f32 %0, %1;" : "=r"(u) : "f"(x));
    return u;
}

#define LDSM4(R, ADDR)                                                          \
    asm volatile("ldmatrix.sync.aligned.m8n8.x4.shared.b16 {%0,%1,%2,%3}, [%4];"\
                 : "=r"(R[0]), "=r"(R[1]), "=r"(R[2]), "=r"(R[3]) : "r"(ADDR))

#define MMA_TF32(D, A, B0, B1)                                                  \
    asm volatile("mma.sync.aligned.m16n8k8.row.col.f32.tf32.tf32.f32 "          \
                 "{%0,%1,%2,%3},{%4,%5,%6,%7},{%8,%9},{%0,%1,%2,%3};"           \
                 : "+f"(D[0]), "+f"(D[1]), "+f"(D[2]), "+f"(D[3])               \
                 : "r"(A[0]), "r"(A[1]), "r"(A[2]), "r"(A[3]), "r"(B0), "r"(B1))

#define CP16(DST, SRC)                                                          \
    asm volatile("cp.async.cg.shared.global [%0], [%1], 16;" :: "r"(DST), "l"(SRC))
#define CP_COMMIT() asm volatile("cp.async.commit_group;")
#define CP_WAIT0()  asm volatile("cp.async.wait_group 0;")

union GemmSmem {
    struct { float As[2][128][20]; float Bs[2][128][20]; } t;   // 40960 B
    struct { float s[128][33]; float q[128][33]; } r;           // 33792 B
};

template <int K, int N, bool BN>
__global__ __launch_bounds__(256, 2)
void gemm_tc(const float* __restrict__ A, const float* __restrict__ W,
             const float* __restrict__ scale, const float* __restrict__ shift,
             float* __restrict__ C,
             float* __restrict__ psum, float* __restrict__ psq) {
    __shared__ GemmSmem sm;

    const int tid  = threadIdx.x;
    const int lane = tid & 31;
    const int warp = tid >> 5;
    const int wm   = warp & 3;
    const int wn   = warp >> 2;
    const int m0   = blockIdx.x * 128;
    const int n0   = blockIdx.y * 128;
    const int l3   = lane & 3;

    // staging: thread -> one row (A: m, B: n), 8 consecutive k (two 16B chunks)
    const int sr = tid & 127;
    const int sc = (tid >> 7) * 8;
    const float* Ap = A + (size_t)(m0 + sr) * K + sc;
    const float* Wp = W + (size_t)(n0 + sr) * K + sc;
    uint32_t sA[2], sB[2];
#pragma unroll
    for (int bu = 0; bu < 2; bu++) {
        sA[bu] = (uint32_t)__cvta_generic_to_shared(&sm.t.As[bu][sr][sc]);
        sB[bu] = (uint32_t)__cvta_generic_to_shared(&sm.t.Bs[bu][sr][sc]);
    }

    // ldmatrix per-lane source addresses (sel = lane>>3 picks sub-matrix)
    const int r8  = lane & 7;
    const int sel = lane >> 3;
    uint32_t a_addr[2][2][2], b_addr[2][4][2];    // [buf][...][chunk]
#pragma unroll
    for (int bu = 0; bu < 2; bu++) {
        uint32_t ab = (uint32_t)__cvta_generic_to_shared(&sm.t.As[bu][0][0]);
        uint32_t bb = (uint32_t)__cvta_generic_to_shared(&sm.t.Bs[bu][0][0]);
#pragma unroll
        for (int mt = 0; mt < 2; mt++)
#pragma unroll
            for (int c = 0; c < 2; c++)
                a_addr[bu][mt][c] = ab +
                    (((wm * 32 + mt * 16) + r8 + (sel & 1) * 8) * 20 + c * 8 + (sel & 2) * 2) * 4;
#pragma unroll
        for (int p = 0; p < 4; p++)
#pragma unroll
            for (int c = 0; c < 2; c++)
                b_addr[bu][p][c] = bb +
                    (((wn * 64 + p * 16) + r8 + (sel >> 1) * 8) * 20 + c * 8 + (sel & 1) * 4) * 4;
    }

    float acc[2][8][4];
#pragma unroll
    for (int mt = 0; mt < 2; mt++)
#pragma unroll
        for (int nt = 0; nt < 8; nt++)
#pragma unroll
            for (int i = 0; i < 4; i++) acc[mt][nt][i] = 0.0f;

    // prologue: issue tile 0
    CP16(sA[0],      Ap);
    CP16(sA[0] + 16, Ap + 4);
    CP16(sB[0],      Wp);
    CP16(sB[0] + 16, Wp + 4);
    CP_COMMIT();

    const int KT = K / 16;
#pragma unroll 1
    for (int kt = 0; kt < KT; kt++) {
        const int buf = kt & 1;
        CP_WAIT0();
        __syncthreads();                 // tile kt resident, prev buffer free
        if (kt + 1 < KT) {
            const int k0n = (kt + 1) * 16;
            const int nb  = buf ^ 1;
            CP16(sA[nb],      Ap + k0n);
            CP16(sA[nb] + 16, Ap + k0n + 4);
            CP16(sB[nb],      Wp + k0n);
            CP16(sB[nb] + 16, Wp + k0n + 4);
            CP_COMMIT();
        }

        // per-tile BN coefficients for this lane's fragment k-channels
        float bns[2][2], bnh[2][2];      // [chunk][khalf]
        if (BN) {
            const int kb = kt * 16 + l3;
#pragma unroll
            for (int c = 0; c < 2; c++)
#pragma unroll
                for (int h = 0; h < 2; h++) {
                    bns[c][h] = scale[kb + c * 8 + h * 4];
                    bnh[c][h] = shift[kb + c * 8 + h * 4];
                }
        }

#pragma unroll
        for (int c = 0; c < 2; c++) {
            uint32_t af[2][4];
            LDSM4(af[0], a_addr[buf][0][c]);
            LDSM4(af[1], a_addr[buf][1][c]);
            uint32_t bf[4][4];
#pragma unroll
            for (int p = 0; p < 4; p++) LDSM4(bf[p], b_addr[buf][p][c]);

#pragma unroll
            for (int mt = 0; mt < 2; mt++)
#pragma unroll
                for (int r = 0; r < 4; r++) {
                    float v = __uint_as_float(af[mt][r]);
                    if (BN) v = fmaxf(fmaf(v, bns[c][(r >> 1) & 1], bnh[c][(r >> 1) & 1]), 0.0f);
                    af[mt][r] = f2tf32(v);
                }
#pragma unroll
            for (int p = 0; p < 4; p++)
#pragma unroll
                for (int r = 0; r < 4; r++)
                    bf[p][r] = f2tf32(__uint_as_float(bf[p][r]));

#pragma unroll
            for (int mt = 0; mt < 2; mt++)
#pragma unroll
                for (int nt = 0; nt < 8; nt++) {
                    const int p = nt >> 1, wh = nt & 1;
                    MMA_TF32(acc[mt][nt], af[mt], bf[p][wh * 2], bf[p][wh * 2 + 1]);
                }
        }
        __syncthreads();                 // all warps done with buf before overwrite
    }

    // ---- write C tile ----
    const int rr = lane >> 2;
    const int cc = l3 * 2;
#pragma unroll
    for (int mt = 0; mt < 2; mt++)
#pragma unroll
        for (int nt = 0; nt < 8; nt++) {
            const int row = m0 + wm * 32 + mt * 16 + rr;
            const int col = n0 + wn * 64 + nt * 8 + cc;
            float2 v0 = { acc[mt][nt][0], acc[mt][nt][1] };
            float2 v1 = { acc[mt][nt][2], acc[mt][nt][3] };
            *(float2*)&C[(size_t)row * N + col]       = v0;
            *(float2*)&C[(size_t)(row + 8) * N + col] = v1;
        }

    // ---- fused per-block BN stats (deterministic fixed-order reduction) ----
    __syncthreads();
    const int contrib = wm * 8 + rr;
#pragma unroll
    for (int nt = 0; nt < 8; nt++)
#pragma unroll
        for (int d = 0; d < 2; d++) {
            const int colL = wn * 64 + nt * 8 + cc + d;
            float s = 0.0f, q = 0.0f;
#pragma unroll
            for (int mt = 0; mt < 2; mt++) {
                float v0 = acc[mt][nt][d];
                float v1 = acc[mt][nt][d + 2];
                s += v0 + v1;
                q += v0 * v0 + v1 * v1;
            }
            sm.r.s[colL][contrib] = s;
            sm.r.q[colL][contrib] = q;
        }
    __syncthreads();
    if (tid < 128) {
        float s = 0.0f, q = 0.0f;
#pragma unroll 8
        for (int i = 0; i < 32; i++) { s += sm.r.s[tid][i]; q += sm.r.q[tid][i]; }
        psum[(size_t)blockIdx.x * N + n0 + tid] = s;
        psq [(size_t)blockIdx.x * N + n0 + tid] = q;
    }
}

// ---------------- parallel BN reduce: one block per channel ----------------
template <int C, int PB>
__global__ void reduce_kernel(const float* __restrict__ psum, const float* __restrict__ psq,
                              const float* __restrict__ gamma, const float* __restrict__ beta,
                              float* __restrict__ scale, float* __restrict__ shift) {
    __shared__ float ss[256], sq[256];
    const int c = blockIdx.x;
    const int t = threadIdx.x;
    float s = 0.0f, q = 0.0f;
    for (int i = t; i < PB; i += 256) {
        s += psum[(size_t)i * C + c];
        q += psq [(size_t)i * C + c];
    }
    ss[t] = s; sq[t] = q;
    __syncthreads();
#pragma unroll
    for (int off = 128; off > 0; off >>= 1) {
        if (t < off) { ss[t] += ss[t + off]; sq[t] += sq[t + off]; }
        __syncthreads();
    }
    if (t == 0) {
        const float invn = 1.0f / (float)M_;
        float mean = ss[0] * invn;
        float var  = sq[0] * invn - mean * mean;
        float sc = gamma[c] * rsqrtf(var + BN_EPS);
        scale[c] = sc;
        shift[c] = beta[c] - mean * sc;
    }
}

// ---------------- final BN2 + ReLU ----------------
__global__ void apply_kernel(const float* __restrict__ H,
                             const float* __restrict__ scale, const float* __restrict__ shift,
                             float* __restrict__ out) {
    size_t i = (size_t)blockIdx.x * blockDim.x + threadIdx.x;
    float4 v = ((const float4*)H)[i];
    int c = (int)((i * 4) & (H2_ - 1));
    float4 o;
    o.x = fmaxf(fmaf(v.x, scale[c + 0], shift[c + 0]), 0.0f);
    o.y = fmaxf(fmaf(v.y, scale[c + 1], shift[c + 1]), 0.0f);
    o.z = fmaxf(fmaf(v.z, scale[c + 2], shift[c + 2]), 0.0f);
    o.w = fmaxf(fmaf(v.w, scale[c + 3], shift[c + 3]), 0.0f);
    ((float4*)out)[i] = o;
}

// ---------------- host launcher ----------------
extern "C" void kernel_launch(void* const* d_in, const int* in_sizes, int n_in,
                              void* d_out, int out_size) {
    const float* xyz1    = (const float*)d_in[0];
    const float* xyz2    = (const float*)d_in[1];
    const float* points1 = (const float*)d_in[2];
    const float* points2 = (const float*)d_in[3];
    const float* W1      = (const float*)d_in[4];   // [256 out][384 in] = n-major
    // d_in[5] = b1 : cancels under BatchNorm -> unused
    const float* gamma1  = (const float*)d_in[6];
    const float* beta1   = (const float*)d_in[7];
    const float* W2      = (const float*)d_in[8];   // [128 out][256 in] = n-major
    // d_in[9] = b2 : cancels under BatchNorm -> unused
    const float* gamma2  = (const float*)d_in[10];
    const float* beta2   = (const float*)d_in[11];
    float* out = (float*)d_out;

    float *px, *ph1, *ph2, *pps, *ppq, *psc1, *psh1, *psc2, *psh2;
    cudaGetSymbolAddress((void**)&px,   g_x);
    cudaGetSymbolAddress((void**)&ph1,  g_h1);
    cudaGetSymbolAddress((void**)&ph2,  g_h2);
    cudaGetSymbolAddress((void**)&pps,  g_psum);
    cudaGetSymbolAddress((void**)&ppq,  g_psq);
    cudaGetSymbolAddress((void**)&psc1, g_scale1);
    cudaGetSymbolAddress((void**)&psh1, g_shift1);
    cudaGetSymbolAddress((void**)&psc2, g_scale2);
    cudaGetSymbolAddress((void**)&psh2, g_shift2);

    // 3-NN + interpolate + concat -> g_x [M,384]
    {
        dim3 grid(N1_ / QPB, B_);
        knn_interp_kernel<<<grid, KNN_T>>>(xyz1, xyz2, points1, points2, px);
    }

    // GEMM1 (tf32 TC, cp.async pipeline) + fused BN1 partial stats
    {
        dim3 grid(MT_, H1_ / 128);
        gemm_tc<INCH_, H1_, false><<<grid, 256>>>(px, W1, nullptr, nullptr, ph1, pps, ppq);
    }
    reduce_kernel<H1_, MT_><<<H1_, 256>>>(pps, ppq, gamma1, beta1, psc1, psh1);

    // GEMM2 (tf32 TC, cp.async pipeline) with fragment-level BN1+ReLU on A
    {
        dim3 grid(MT_, H2_ / 128);
        gemm_tc<H1_, H2_, true><<<grid, 256>>>(ph1, W2, psc1, psh1, ph2, pps, ppq);
    }
    reduce_kernel<H2_, MT_><<<H2_, 256>>>(pps, ppq, gamma2, beta2, psc2, psh2);

    // final BN2 + ReLU -> d_out [M,128]
    {
        size_t n4 = (size_t)M_ * H2_ / 4;
        apply_kernel<<<(unsigned)(n4 / 256), 256>>>(ph2, psc2, psh2, out);
    }
}